// round 3
// baseline (speedup 1.0000x reference)
#include <cuda_runtime.h>
#include <cstdint>

#define NN 50000
#define EE 800000
#define FIN 500
#define HH 64
#define CO 16

// ---------------- scratch (device globals; allocation-free) ----------------
__device__ float g_xw_a[NN * HH];
__device__ float g_xw_b[NN * HH];
__device__ float g_agg_a[NN * HH];
__device__ float g_agg_b[NN * HH];
__device__ float g_h[NN * 2 * HH];
__device__ float g_xw_l[NN * CO];
__device__ float g_agg_l[NN * CO];
__device__ float g_coef_dir[EE];   // sign encodes branch: + => st (xw_a), - => ts (xw_b)
__device__ float g_coef_all[EE];
__device__ float g_deg_st[NN], g_deg_ts[NN], g_deg_all[NN];
__device__ float g_dinv_st[NN], g_dinv_ts[NN], g_dinv_all[NN];
__device__ int   g_flags[2];       // [0]=saw_float_bits, [1]=saw_byte_layout

// ---------------- helpers ----------------
__device__ __forceinline__ int edge_reversed(const void* m, int e) {
    if (g_flags[1]) return ((const unsigned char*)m)[e] != 0;
    if (g_flags[0]) return ((const float*)m)[e] != 0.0f;
    return ((const int*)m)[e] != 0;
}

__device__ __forceinline__ void agg_add4(float* p, float4 v) {
    atomicAdd(p + 0, v.x);
    atomicAdd(p + 1, v.y);
    atomicAdd(p + 2, v.z);
    atomicAdd(p + 3, v.w);
}

// ---------------- zero / probe ----------------
__global__ void k_zero_small() {
    int i = blockIdx.x * blockDim.x + threadIdx.x;
    if (i < NN) { g_deg_st[i] = 0.f; g_deg_ts[i] = 0.f; g_deg_all[i] = 0.f; }
    if (i < 2) g_flags[i] = 0;
}

__global__ void k_zero_agg64() {
    int i = blockIdx.x * blockDim.x + threadIdx.x;  // float4 index
    if (i < NN * HH / 4) {
        ((float4*)g_agg_a)[i] = make_float4(0.f, 0.f, 0.f, 0.f);
        ((float4*)g_agg_b)[i] = make_float4(0.f, 0.f, 0.f, 0.f);
    }
}

__global__ void k_zero_agg16() {
    int i = blockIdx.x * blockDim.x + threadIdx.x;
    if (i < NN * CO / 4) ((float4*)g_agg_l)[i] = make_float4(0.f, 0.f, 0.f, 0.f);
}

// Probe the storage layout of is_reversed. Scanning 200000 words is safe:
// float32/int32 layouts have 800000 words; uint8 layout has exactly 200000.
__global__ void k_detect(const unsigned int* __restrict__ m) {
    int i = blockIdx.x * blockDim.x + threadIdx.x;
    unsigned int sawF = 0, sawB = 0;
    if (i < 200000) {
        unsigned int w = m[i];
        if (w > 1u) { if (w == 0x3F800000u) sawF = 1; else sawB = 1; }
    }
    sawF = __any_sync(0xFFFFFFFF, sawF);
    sawB = __any_sync(0xFFFFFFFF, sawB);
    if ((threadIdx.x & 31) == 0) {
        if (sawF) atomicOr(&g_flags[0], 1);
        if (sawB) atomicOr(&g_flags[1], 1);
    }
}

// ---------------- degrees / normalization ----------------
__global__ void k_degree(const int* __restrict__ src, const int* __restrict__ dst,
                         const void* __restrict__ mrev) {
    int e = blockIdx.x * blockDim.x + threadIdx.x;
    if (e >= EE) return;
    int d = dst[e];
    if (edge_reversed(mrev, e)) atomicAdd(&g_deg_ts[d], 1.f);
    else                        atomicAdd(&g_deg_st[d], 1.f);
    atomicAdd(&g_deg_all[d], 1.f);
}

__global__ void k_dinv() {
    int n = blockIdx.x * blockDim.x + threadIdx.x;
    if (n >= NN) return;
    g_dinv_st[n]  = rsqrtf(g_deg_st[n]  + 1.f);
    g_dinv_ts[n]  = rsqrtf(g_deg_ts[n]  + 1.f);
    g_dinv_all[n] = rsqrtf(g_deg_all[n] + 1.f);
}

__global__ void k_coef(const int* __restrict__ src, const int* __restrict__ dst,
                       const void* __restrict__ mrev) {
    int e = blockIdx.x * blockDim.x + threadIdx.x;
    if (e >= EE) return;
    int s = src[e], d = dst[e];
    int rev = edge_reversed(mrev, e);
    float c = rev ? (g_dinv_ts[s] * g_dinv_ts[d]) : (g_dinv_st[s] * g_dinv_st[d]);
    g_coef_dir[e] = rev ? -c : c;
    g_coef_all[e] = g_dinv_all[s] * g_dinv_all[d];
}

// ---------------- GEMM: C[M,128] = A[M,K] @ [Wa | Wb]  (each W is [K,64]) ----------------
__global__ __launch_bounds__(256, 2)
void k_gemm128(const float* __restrict__ Aparam, int M, int K,
               const float* __restrict__ Wa, const float* __restrict__ Wb,
               int asel) {
    const float* A = asel ? g_h : Aparam;
    __shared__ float As[8 * 128];
    __shared__ float Bs[8 * 128];
    int tid = threadIdx.x;
    int r0 = (tid >> 4) * 8;
    int c0 = (tid & 15) * 8;
    int bm = blockIdx.x * 128;

    int arow  = tid >> 1;         // 0..127
    int akoff = (tid & 1) * 4;    // 0 or 4
    int bkk   = tid >> 5;         // 0..7
    int bc    = (tid & 31) * 4;   // 0..124

    float acc[8][8];
#pragma unroll
    for (int i = 0; i < 8; i++)
#pragma unroll
        for (int j = 0; j < 8; j++) acc[i][j] = 0.f;

    for (int k0 = 0; k0 < K; k0 += 8) {
        float4 av = make_float4(0.f, 0.f, 0.f, 0.f);
        int grow = bm + arow;
        int gk = k0 + akoff;
        if (grow < M && gk < K)  // K multiple of 4, gk aligned -> full float4 valid
            av = *(const float4*)(A + (size_t)grow * K + gk);
        As[(akoff + 0) * 128 + arow] = av.x;
        As[(akoff + 1) * 128 + arow] = av.y;
        As[(akoff + 2) * 128 + arow] = av.z;
        As[(akoff + 3) * 128 + arow] = av.w;

        float4 bv = make_float4(0.f, 0.f, 0.f, 0.f);
        int bk = k0 + bkk;
        if (bk < K) {
            if (bc < 64) bv = *(const float4*)(Wa + bk * 64 + bc);
            else         bv = *(const float4*)(Wb + bk * 64 + (bc - 64));
        }
        *(float4*)&Bs[bkk * 128 + bc] = bv;
        __syncthreads();

#pragma unroll
        for (int kk = 0; kk < 8; kk++) {
            float4 a0 = *(const float4*)&As[kk * 128 + r0];
            float4 a1 = *(const float4*)&As[kk * 128 + r0 + 4];
            float4 b0 = *(const float4*)&Bs[kk * 128 + c0];
            float4 b1 = *(const float4*)&Bs[kk * 128 + c0 + 4];
            float ar[8] = {a0.x, a0.y, a0.z, a0.w, a1.x, a1.y, a1.z, a1.w};
            float br[8] = {b0.x, b0.y, b0.z, b0.w, b1.x, b1.y, b1.z, b1.w};
#pragma unroll
            for (int i = 0; i < 8; i++)
#pragma unroll
                for (int j = 0; j < 8; j++)
                    acc[i][j] = fmaf(ar[i], br[j], acc[i][j]);
        }
        __syncthreads();
    }

    float* C = (c0 < 64) ? g_xw_a : g_xw_b;
    int ccol = (c0 < 64) ? c0 : c0 - 64;
#pragma unroll
    for (int i = 0; i < 8; i++) {
        int row = bm + r0 + i;
        if (row < M) {
            *(float4*)(C + (size_t)row * 64 + ccol)     = make_float4(acc[i][0], acc[i][1], acc[i][2], acc[i][3]);
            *(float4*)(C + (size_t)row * 64 + ccol + 4) = make_float4(acc[i][4], acc[i][5], acc[i][6], acc[i][7]);
        }
    }
}

// ---------------- edge scatter (fused st/ts via signed coef) ----------------
__global__ void k_scatter64(const int* __restrict__ src, const int* __restrict__ dst) {
    int idx = blockIdx.x * blockDim.x + threadIdx.x;
    int e = idx >> 4;           // 16 float4 chunks per 64-channel row
    int q = idx & 15;
    if (e >= EE) return;
    float c = g_coef_dir[e];
    const float4* xw;
    float* agg;
    if (c < 0.f) { c = -c; xw = (const float4*)g_xw_b; agg = g_agg_b; }
    else         {          xw = (const float4*)g_xw_a; agg = g_agg_a; }
    int s = src[e], d = dst[e];
    float4 v = xw[s * 16 + q];
    v.x *= c; v.y *= c; v.z *= c; v.w *= c;
    agg_add4(agg + d * 64 + q * 4, v);
}

__global__ void k_scatter16(const int* __restrict__ src, const int* __restrict__ dst) {
    int idx = blockIdx.x * blockDim.x + threadIdx.x;
    int e = idx >> 2;           // 4 float4 chunks per 16-channel row
    int q = idx & 3;
    if (e >= EE) return;
    float c = g_coef_all[e];
    int s = src[e], d = dst[e];
    float4 v = ((const float4*)g_xw_l)[s * 4 + q];
    v.x *= c; v.y *= c; v.z *= c; v.w *= c;
    agg_add4(g_agg_l + d * 16 + q * 4, v);
}

// ---------------- combine (agg + self-loop + bias, relu) -> h ----------------
__global__ void k_combine(const float* __restrict__ b_st, const float* __restrict__ b_ts) {
    int idx = blockIdx.x * blockDim.x + threadIdx.x;   // n*128 + c
    int n = idx >> 7;
    int c = idx & 127;
    if (n >= NN) return;
    int second = c >= 64;
    int cc = c & 63;
    float dinv = second ? g_dinv_ts[n] : g_dinv_st[n];
    float xw   = (second ? g_xw_b : g_xw_a)[n * 64 + cc];
    float agg  = (second ? g_agg_b : g_agg_a)[n * 64 + cc];
    float bias = second ? b_ts[cc] : b_st[cc];
    float v = agg + xw * dinv * dinv + bias;
    g_h[idx] = fmaxf(v, 0.f);
}

// ---------------- last layer: xw_l = h @ W_last ----------------
__global__ void k_gemm16(const float* __restrict__ Wl) {
    __shared__ float Ws[128 * 16];
    for (int i = threadIdx.x; i < 128 * 16; i += blockDim.x) Ws[i] = Wl[i];
    __syncthreads();
    int idx = blockIdx.x * blockDim.x + threadIdx.x;
    int n = idx >> 4;
    int j = idx & 15;
    if (n >= NN) return;
    const float* hr = g_h + (size_t)n * 128;
    float acc = 0.f;
#pragma unroll
    for (int k = 0; k < 128; k++) acc = fmaf(hr[k], Ws[k * 16 + j], acc);
    g_xw_l[n * 16 + j] = acc;
}

// ---------------- final combine + log_softmax ----------------
__global__ void k_final(const float* __restrict__ b_last, float* __restrict__ out) {
    int n = blockIdx.x * blockDim.x + threadIdx.x;
    if (n >= NN) return;
    float dinv = g_dinv_all[n];
    float d2 = dinv * dinv;
    float v[CO];
    float m = -1e30f;
#pragma unroll
    for (int c = 0; c < CO; c++) {
        v[c] = g_agg_l[n * CO + c] + g_xw_l[n * CO + c] * d2 + b_last[c];
        m = fmaxf(m, v[c]);
    }
    float s = 0.f;
#pragma unroll
    for (int c = 0; c < CO; c++) s += expf(v[c] - m);
    float ls = logf(s) + m;
#pragma unroll
    for (int c = 0; c < CO; c++) out[n * CO + c] = v[c] - ls;
}

// ---------------- launch ----------------
extern "C" void kernel_launch(void* const* d_in, const int* in_sizes, int n_in,
                              void* d_out, int out_size) {
    const float* x      = (const float*)d_in[0];
    const int*   ei     = (const int*)d_in[1];
    const void*  mrev   = d_in[2];
    const float* W_st0  = (const float*)d_in[3];
    const float* b_st0  = (const float*)d_in[4];
    const float* W_ts0  = (const float*)d_in[5];
    const float* b_ts0  = (const float*)d_in[6];
    const float* W_st1  = (const float*)d_in[7];
    const float* b_st1  = (const float*)d_in[8];
    const float* W_ts1  = (const float*)d_in[9];
    const float* b_ts1  = (const float*)d_in[10];
    const float* W_last = (const float*)d_in[11];
    const float* b_last = (const float*)d_in[12];
    float* out = (float*)d_out;

    const int* srcp = ei;
    const int* dstp = ei + EE;
    const int TB = 256;

    // graph prep
    k_zero_small<<<(NN + TB - 1) / TB, TB>>>();
    k_detect<<<(200000 + TB - 1) / TB, TB>>>((const unsigned int*)mrev);
    k_degree<<<(EE + TB - 1) / TB, TB>>>(srcp, dstp, mrev);
    k_dinv<<<(NN + TB - 1) / TB, TB>>>();
    k_coef<<<(EE + TB - 1) / TB, TB>>>(srcp, dstp, mrev);

    const int GEMM_BLOCKS = (NN + 127) / 128;

    // layer 0
    k_gemm128<<<GEMM_BLOCKS, 256>>>(x, NN, FIN, W_st0, W_ts0, 0);
    k_zero_agg64<<<(NN * HH / 4 + TB - 1) / TB, TB>>>();
    k_scatter64<<<(EE * 16 + TB - 1) / TB, TB>>>(srcp, dstp);
    k_combine<<<(NN * 128) / TB, TB>>>(b_st0, b_ts0);

    // layer 1
    k_gemm128<<<GEMM_BLOCKS, 256>>>(nullptr, NN, 2 * HH, W_st1, W_ts1, 1);
    k_zero_agg64<<<(NN * HH / 4 + TB - 1) / TB, TB>>>();
    k_scatter64<<<(EE * 16 + TB - 1) / TB, TB>>>(srcp, dstp);
    k_combine<<<(NN * 128) / TB, TB>>>(b_st1, b_ts1);

    // last layer
    k_gemm16<<<(NN * 16) / TB, TB>>>(W_last);
    k_zero_agg16<<<(NN * CO / 4 + TB - 1) / TB, TB>>>();
    k_scatter16<<<(EE * 4) / TB, TB>>>(srcp, dstp);
    k_final<<<(NN + TB - 1) / TB, TB>>>(b_last, out);
}

// round 5
// speedup vs baseline: 1.2156x; 1.2156x over previous
#include <cuda_runtime.h>
#include <cstdint>

#define NN 50000
#define EE 800000
#define FIN 500
#define HH 64
#define CO 16
#define SCAN_T 1024
#define SCAN_CH 49   // ceil(NN/1024)

// ---------------- scratch (device globals; allocation-free) ----------------
__device__ float g_xw_a[NN * HH];
__device__ float g_xw_b[NN * HH];
__device__ float g_h[NN * 2 * HH];
__device__ float g_xw_l[NN * CO];
__device__ int   g_degi_st[NN], g_degi_ts[NN];
__device__ int   g_rowstart[NN + 1];
__device__ int   g_cursor[NN];
__device__ int   g_src_sorted[EE];
__device__ float g_cdir_sorted[EE];   // sign encodes branch: + => st (xw_a), - => ts (xw_b)
__device__ float g_call_sorted[EE];
__device__ float g_dinv_st[NN], g_dinv_ts[NN], g_dinv_all[NN];
__device__ int   g_flags[2];          // [0]=saw_float_bits, [1]=saw_byte_layout

// ---------------- helpers ----------------
__device__ __forceinline__ int edge_reversed(const void* m, int e) {
    if (g_flags[1]) return ((const unsigned char*)m)[e] != 0;
    if (g_flags[0]) return ((const float*)m)[e] != 0.0f;
    return ((const int*)m)[e] != 0;
}

// ---------------- zero / probe ----------------
__global__ void k_zero_small() {
    int i = blockIdx.x * blockDim.x + threadIdx.x;
    if (i < NN) { g_degi_st[i] = 0; g_degi_ts[i] = 0; g_cursor[i] = 0; }
    if (i < 2) g_flags[i] = 0;
}

// Probe the storage layout of is_reversed. Scanning 200000 words is safe:
// float32/int32 layouts have 800000 words; uint8 layout has exactly 200000.
__global__ void k_detect(const unsigned int* __restrict__ m) {
    int i = blockIdx.x * blockDim.x + threadIdx.x;
    unsigned int sawF = 0, sawB = 0;
    if (i < 200000) {
        unsigned int w = m[i];
        if (w > 1u) { if (w == 0x3F800000u) sawF = 1; else sawB = 1; }
    }
    sawF = __any_sync(0xFFFFFFFF, sawF);
    sawB = __any_sync(0xFFFFFFFF, sawB);
    if ((threadIdx.x & 31) == 0) {
        if (sawF) atomicOr(&g_flags[0], 1);
        if (sawB) atomicOr(&g_flags[1], 1);
    }
}

// ---------------- degree histogram (int atomics) ----------------
__global__ void k_hist(const int* __restrict__ dst, const void* __restrict__ mrev) {
    int e = blockIdx.x * blockDim.x + threadIdx.x;
    if (e >= EE) return;
    int d = dst[e];
    if (edge_reversed(mrev, e)) atomicAdd(&g_degi_ts[d], 1);
    else                        atomicAdd(&g_degi_st[d], 1);
}

__global__ void k_dinv() {
    int n = blockIdx.x * blockDim.x + threadIdx.x;
    if (n >= NN) return;
    float ds = (float)g_degi_st[n], dt = (float)g_degi_ts[n];
    g_dinv_st[n]  = rsqrtf(ds + 1.f);
    g_dinv_ts[n]  = rsqrtf(dt + 1.f);
    g_dinv_all[n] = rsqrtf(ds + dt + 1.f);
}

// ---------------- exclusive scan of total degree -> rowstart (single block) ----------------
__global__ void k_scan() {
    int t = threadIdx.x;
    int begin = t * SCAN_CH;
    int end = begin + SCAN_CH; if (end > NN) end = NN;
    int local = 0;
    for (int i = begin; i < end; i++) local += g_degi_st[i] + g_degi_ts[i];

    int lane = t & 31, wid = t >> 5;
    int v = local;
#pragma unroll
    for (int o = 1; o < 32; o <<= 1) {
        int u = __shfl_up_sync(0xFFFFFFFF, v, o);
        if (lane >= o) v += u;
    }
    __shared__ int ws[32];
    if (lane == 31) ws[wid] = v;
    __syncthreads();
    if (wid == 0) {
        int s = ws[lane];
#pragma unroll
        for (int o = 1; o < 32; o <<= 1) {
            int u = __shfl_up_sync(0xFFFFFFFF, s, o);
            if (lane >= o) s += u;
        }
        ws[lane] = s;
    }
    __syncthreads();
    int excl = v - local + (wid > 0 ? ws[wid - 1] : 0);
    int run = excl;
    for (int i = begin; i < end; i++) {
        g_rowstart[i] = run;
        run += g_degi_st[i] + g_degi_ts[i];
    }
    if (t == SCAN_T - 1) g_rowstart[NN] = run;   // == EE
}

// ---------------- fill CSR buckets with src + coefficients ----------------
__global__ void k_fill(const int* __restrict__ src, const int* __restrict__ dst,
                       const void* __restrict__ mrev) {
    int e = blockIdx.x * blockDim.x + threadIdx.x;
    if (e >= EE) return;
    int s = src[e], d = dst[e];
    int rev = edge_reversed(mrev, e);
    int pos = g_rowstart[d] + atomicAdd(&g_cursor[d], 1);
    float c = rev ? (g_dinv_ts[s] * g_dinv_ts[d]) : (g_dinv_st[s] * g_dinv_st[d]);
    g_src_sorted[pos]  = s;
    g_cdir_sorted[pos] = rev ? -c : c;
    g_call_sorted[pos] = g_dinv_all[s] * g_dinv_all[d];
}

// ---------------- GEMM: C[M,128] = A[M,K] @ [Wa | Wb]  (each W is [K,64]) ----------------
__global__ __launch_bounds__(256, 2)
void k_gemm128(const float* __restrict__ Aparam, int M, int K,
               const float* __restrict__ Wa, const float* __restrict__ Wb,
               int asel) {
    const float* A = asel ? g_h : Aparam;
    __shared__ float As[8 * 128];
    __shared__ float Bs[8 * 128];
    int tid = threadIdx.x;
    int r0 = (tid >> 4) * 8;
    int c0 = (tid & 15) * 8;
    int bm = blockIdx.x * 128;

    int arow  = tid >> 1;         // 0..127
    int akoff = (tid & 1) * 4;    // 0 or 4
    int bkk   = tid >> 5;         // 0..7
    int bc    = (tid & 31) * 4;   // 0..124

    float acc[8][8];
#pragma unroll
    for (int i = 0; i < 8; i++)
#pragma unroll
        for (int j = 0; j < 8; j++) acc[i][j] = 0.f;

    for (int k0 = 0; k0 < K; k0 += 8) {
        float4 av = make_float4(0.f, 0.f, 0.f, 0.f);
        int grow = bm + arow;
        int gk = k0 + akoff;
        if (grow < M && gk < K)
            av = *(const float4*)(A + (size_t)grow * K + gk);
        As[(akoff + 0) * 128 + arow] = av.x;
        As[(akoff + 1) * 128 + arow] = av.y;
        As[(akoff + 2) * 128 + arow] = av.z;
        As[(akoff + 3) * 128 + arow] = av.w;

        float4 bv = make_float4(0.f, 0.f, 0.f, 0.f);
        int bk = k0 + bkk;
        if (bk < K) {
            if (bc < 64) bv = *(const float4*)(Wa + bk * 64 + bc);
            else         bv = *(const float4*)(Wb + bk * 64 + (bc - 64));
        }
        *(float4*)&Bs[bkk * 128 + bc] = bv;
        __syncthreads();

#pragma unroll
        for (int kk = 0; kk < 8; kk++) {
            float4 a0 = *(const float4*)&As[kk * 128 + r0];
            float4 a1 = *(const float4*)&As[kk * 128 + r0 + 4];
            float4 b0 = *(const float4*)&Bs[kk * 128 + c0];
            float4 b1 = *(const float4*)&Bs[kk * 128 + c0 + 4];
            float ar[8] = {a0.x, a0.y, a0.z, a0.w, a1.x, a1.y, a1.z, a1.w};
            float br[8] = {b0.x, b0.y, b0.z, b0.w, b1.x, b1.y, b1.z, b1.w};
#pragma unroll
            for (int i = 0; i < 8; i++)
#pragma unroll
                for (int j = 0; j < 8; j++)
                    acc[i][j] = fmaf(ar[i], br[j], acc[i][j]);
        }
        __syncthreads();
    }

    float* C = (c0 < 64) ? g_xw_a : g_xw_b;
    int ccol = (c0 < 64) ? c0 : c0 - 64;
#pragma unroll
    for (int i = 0; i < 8; i++) {
        int row = bm + r0 + i;
        if (row < M) {
            *(float4*)(C + (size_t)row * 64 + ccol)     = make_float4(acc[i][0], acc[i][1], acc[i][2], acc[i][3]);
            *(float4*)(C + (size_t)row * 64 + ccol + 4) = make_float4(acc[i][4], acc[i][5], acc[i][6], acc[i][7]);
        }
    }
}

// ---------------- gather aggregation (both branches) + combine + relu -> h ----------------
// block = node, 64 threads = channels. No atomics.
__global__ __launch_bounds__(64)
void k_gather64(const float* __restrict__ b_st, const float* __restrict__ b_ts) {
    int n = blockIdx.x;
    int c = threadIdx.x;
    int rs = g_rowstart[n], re = g_rowstart[n + 1];
    float acc_a = 0.f, acc_b = 0.f;
    int i = rs;
    // 2-way ILP over edges
    for (; i + 1 < re; i += 2) {
        int   s0 = g_src_sorted[i],     s1 = g_src_sorted[i + 1];
        float c0 = g_cdir_sorted[i],    c1 = g_cdir_sorted[i + 1];
        float v0 = (c0 >= 0.f) ? g_xw_a[s0 * 64 + c] : g_xw_b[s0 * 64 + c];
        float v1 = (c1 >= 0.f) ? g_xw_a[s1 * 64 + c] : g_xw_b[s1 * 64 + c];
        if (c0 >= 0.f) acc_a = fmaf(c0, v0, acc_a); else acc_b = fmaf(-c0, v0, acc_b);
        if (c1 >= 0.f) acc_a = fmaf(c1, v1, acc_a); else acc_b = fmaf(-c1, v1, acc_b);
    }
    if (i < re) {
        int   s0 = g_src_sorted[i];
        float c0 = g_cdir_sorted[i];
        float v0 = (c0 >= 0.f) ? g_xw_a[s0 * 64 + c] : g_xw_b[s0 * 64 + c];
        if (c0 >= 0.f) acc_a = fmaf(c0, v0, acc_a); else acc_b = fmaf(-c0, v0, acc_b);
    }
    float da = g_dinv_st[n], db = g_dinv_ts[n];
    float va = acc_a + g_xw_a[n * 64 + c] * da * da + b_st[c];
    float vb = acc_b + g_xw_b[n * 64 + c] * db * db + b_ts[c];
    g_h[n * 128 + c]      = fmaxf(va, 0.f);
    g_h[n * 128 + 64 + c] = fmaxf(vb, 0.f);
}

// ---------------- last layer: xw_l = h @ W_last ----------------
__global__ void k_gemm16(const float* __restrict__ Wl) {
    __shared__ float Ws[128 * 16];
    for (int i = threadIdx.x; i < 128 * 16; i += blockDim.x) Ws[i] = Wl[i];
    __syncthreads();
    int idx = blockIdx.x * blockDim.x + threadIdx.x;
    int n = idx >> 4;
    int j = idx & 15;
    if (n >= NN) return;
    const float* hr = g_h + (size_t)n * 128;
    float acc = 0.f;
#pragma unroll
    for (int k = 0; k < 128; k++) acc = fmaf(hr[k], Ws[k * 16 + j], acc);
    g_xw_l[n * 16 + j] = acc;
}

// ---------------- final gather + combine + log_softmax -> out ----------------
// 128 threads = 8 nodes x 16 lanes. NN % 8 == 0 so no partial blocks.
__global__ __launch_bounds__(128)
void k_gather16_final(const float* __restrict__ b_last, float* __restrict__ out) {
    int lid = threadIdx.x & 15;
    int grp = threadIdx.x >> 4;
    int n = blockIdx.x * 8 + grp;
    int rs = g_rowstart[n], re = g_rowstart[n + 1];
    float acc = 0.f;
    for (int i = rs; i < re; i++) {
        int   s = g_src_sorted[i];
        float cf = g_call_sorted[i];
        acc = fmaf(cf, g_xw_l[s * 16 + lid], acc);
    }
    float dinv = g_dinv_all[n];
    float v = acc + g_xw_l[n * 16 + lid] * dinv * dinv + b_last[lid];
    float m = v;
#pragma unroll
    for (int o = 8; o > 0; o >>= 1) m = fmaxf(m, __shfl_xor_sync(0xFFFFFFFF, m, o, 16));
    float ex = expf(v - m);
    float ssum = ex;
#pragma unroll
    for (int o = 8; o > 0; o >>= 1) ssum += __shfl_xor_sync(0xFFFFFFFF, ssum, o, 16);
    out[n * 16 + lid] = v - (logf(ssum) + m);
}

// ---------------- launch ----------------
extern "C" void kernel_launch(void* const* d_in, const int* in_sizes, int n_in,
                              void* d_out, int out_size) {
    const float* x      = (const float*)d_in[0];
    const int*   ei     = (const int*)d_in[1];
    const void*  mrev   = d_in[2];
    const float* W_st0  = (const float*)d_in[3];
    const float* b_st0  = (const float*)d_in[4];
    const float* W_ts0  = (const float*)d_in[5];
    const float* b_ts0  = (const float*)d_in[6];
    const float* W_st1  = (const float*)d_in[7];
    const float* b_st1  = (const float*)d_in[8];
    const float* W_ts1  = (const float*)d_in[9];
    const float* b_ts1  = (const float*)d_in[10];
    const float* W_last = (const float*)d_in[11];
    const float* b_last = (const float*)d_in[12];
    float* out = (float*)d_out;

    const int* srcp = ei;
    const int* dstp = ei + EE;
    const int TB = 256;

    // CSR build + normalization
    k_zero_small<<<(NN + TB - 1) / TB, TB>>>();
    k_detect<<<(200000 + TB - 1) / TB, TB>>>((const unsigned int*)mrev);
    k_hist<<<(EE + TB - 1) / TB, TB>>>(dstp, mrev);
    k_dinv<<<(NN + TB - 1) / TB, TB>>>();
    k_scan<<<1, SCAN_T>>>();
    k_fill<<<(EE + TB - 1) / TB, TB>>>(srcp, dstp, mrev);

    const int GEMM_BLOCKS = (NN + 127) / 128;

    // layer 0
    k_gemm128<<<GEMM_BLOCKS, 256>>>(x, NN, FIN, W_st0, W_ts0, 0);
    k_gather64<<<NN, 64>>>(b_st0, b_ts0);

    // layer 1
    k_gemm128<<<GEMM_BLOCKS, 256>>>(nullptr, NN, 2 * HH, W_st1, W_ts1, 1);
    k_gather64<<<NN, 64>>>(b_st1, b_ts1);

    // last layer
    k_gemm16<<<(NN * 16) / TB, TB>>>(W_last);
    k_gather16_final<<<NN / 8, 128>>>(b_last, out);
}